// round 7
// baseline (speedup 1.0000x reference)
#include <cuda_runtime.h>
#include <cuda_bf16.h>
#include <math.h>
#include <stdint.h>

// ---- problem constants ----
#define BB 16
#define CC 256
#define HH 96
#define WW 96
#define HWP (HH*WW)                 // 9216
#define NELEM (BB*CC*HWP)           // 37748736
#define S0 24
#define S1 48
#define S2 72

// ---- scratch (device globals: allocation-free rule) ----
__device__ __nv_bfloat16 g_zh[NELEM];
__device__ __nv_bfloat16 g_zl[NELEM];
__device__ __nv_bfloat16 g_wh[CC*CC];
__device__ __nv_bfloat16 g_wl[CC*CC];
__device__ float g_dogk[CC*3];

// ===========================================================================
// PTX helpers
// ===========================================================================
__device__ __forceinline__ uint32_t smem_u32(const void* p) {
    uint32_t a;
    asm("{ .reg .u64 t; cvta.to.shared.u64 t, %1; cvt.u32.u64 %0, t; }"
        : "=r"(a) : "l"(p));
    return a;
}
#define CP16(dst, src) asm volatile( \
    "cp.async.cg.shared.global [%0], [%1], 16;" :: "r"(dst), "l"(src) : "memory")
#define CP_COMMIT() asm volatile("cp.async.commit_group;" ::: "memory")
#define CP_WAIT1() asm volatile("cp.async.wait_group 1;" ::: "memory")
#define CP_WAIT0() asm volatile("cp.async.wait_group 0;" ::: "memory")

__device__ __forceinline__ void ldsm_x4(uint32_t* r, uint32_t addr) {
    asm volatile("ldmatrix.sync.aligned.m8n8.x4.shared.b16 {%0,%1,%2,%3}, [%4];"
                 : "=r"(r[0]), "=r"(r[1]), "=r"(r[2]), "=r"(r[3]) : "r"(addr));
}
__device__ __forceinline__ void ldsm_x4_t(uint32_t* r, uint32_t addr) {
    asm volatile("ldmatrix.sync.aligned.m8n8.x4.trans.shared.b16 {%0,%1,%2,%3}, [%4];"
                 : "=r"(r[0]), "=r"(r[1]), "=r"(r[2]), "=r"(r[3]) : "r"(addr));
}
__device__ __forceinline__ void mma_bf16(float* c, const uint32_t* a, const uint32_t* b) {
    asm volatile(
        "mma.sync.aligned.m16n8k16.row.col.f32.bf16.bf16.f32 "
        "{%0,%1,%2,%3}, {%4,%5,%6,%7}, {%8,%9}, {%0,%1,%2,%3};"
        : "+f"(c[0]), "+f"(c[1]), "+f"(c[2]), "+f"(c[3])
        : "r"(a[0]), "r"(a[1]), "r"(a[2]), "r"(a[3]), "r"(b[0]), "r"(b[1]));
}

// ===========================================================================
// K0: per-channel DoG difference-kernel coefficients
// ===========================================================================
__global__ void k_params(const float* __restrict__ s1r, const float* __restrict__ s2r) {
    int c = threadIdx.x;
    float s1 = 2.f / (1.f + expf(-s1r[c]));
    float s2 = 2.f / (1.f + expf(-s2r[c]));
    float e1 = expf(-1.f / (2.f * s1 * s1)); float q1 = expf(-1.f / (s1 * s1));
    float e2 = expf(-1.f / (2.f * s2 * s2)); float q2 = expf(-1.f / (s2 * s2));
    float n1 = 1.f + 4.f * e1 + 4.f * q1;
    float n2 = 1.f + 4.f * e2 + 4.f * q2;
    g_dogk[c*3+0] = 1.f/n1 - 1.f/n2;
    g_dogk[c*3+1] = e1/n1 - e2/n2;
    g_dogk[c*3+2] = q1/n1 - q2/n2;
}

// K0b: split mixer weight into bf16 hi/lo
__global__ void k_wsplit(const float* __restrict__ w) {
    int i = blockIdx.x * 256 + threadIdx.x;
    float v = w[i];
    __nv_bfloat16 h = __float2bfloat16(v);
    g_wh[i] = h;
    g_wl[i] = __float2bfloat16(v - __bfloat162float(h));
}

// ===========================================================================
// K1: fused per-plane elementwise chain. One CTA / (b,c) plane, 512 threads.
//   Phase 3 processes 2x2 pixel quads (shared DoG window + shared tap grids).
// ===========================================================================
#define SMF_Y  0
#define SMF_D0 9216
#define SMF_D1 (9216+576)
#define SMF_D2 (9216+2880)
#define PLANE_SMEM ((9216+8064)*4)   // 69120 B dynamic
#define PT 512

__global__ void __launch_bounds__(PT) k_plane(const float4* __restrict__ dec,
                                              const float4* __restrict__ skip,
                                              const float* __restrict__ wfea) {
    extern __shared__ float sm[];
    __shared__ int   s_ui[3][96];
    __shared__ float s_uw[3][96];
    __shared__ int   s_di[144];
    __shared__ float s_dw[144];

    int bc = blockIdx.x;
    int c  = bc % CC;
    int t  = threadIdx.x;

    // 0) fill coordinate tables
    if (t < 288) {
        int s = t / 96, o = t % 96;
        float scl = (s == 0) ? (S0/96.f) : (s == 1) ? (S1/96.f) : (S2/96.f);
        int S = (s == 0) ? S0 : (s == 1) ? S1 : S2;
        float f = fmaxf((o + 0.5f) * scl - 0.5f, 0.f);
        int i0 = (int)f;
        if (i0 > S - 1) i0 = S - 1;
        s_ui[s][o] = i0;
        s_uw[s][o] = f - (float)i0;
    } else if (t < 432) {
        int u = t - 288;
        int s = (u < 24) ? 0 : (u < 72) ? 1 : 2;
        int o = (s == 0) ? u : (s == 1) ? u - 24 : u - 72;
        float sf = (s == 0) ? (96.f/S0) : (s == 1) ? (96.f/S1) : (96.f/S2);
        float f = fmaxf((o + 0.5f) * sf - 0.5f, 0.f);
        int i0 = (int)f;
        s_di[u] = i0;
        s_dw[u] = f - (float)i0;
    }

    // 1) y = dec + skip into smem
    const float4* dp = dec  + (size_t)bc * (HWP/4);
    const float4* sp = skip + (size_t)bc * (HWP/4);
    float4* y4 = (float4*)(sm + SMF_Y);
#pragma unroll
    for (int k = 0; k < 5; k++) {
        int i = k * PT + t;
        if (i < HWP/4) {
            float4 a = dp[i], b = sp[i];
            y4[i] = make_float4(a.x + b.x, a.y + b.y, a.z + b.z, a.w + b.w);
        }
    }
    __syncthreads();

    const float* sy = sm + SMF_Y;

    // 2) three bilinear downsamples into smem (8064 outputs) via tables
#pragma unroll
    for (int k = 0; k < 16; k++) {
        int i = k * PT + t;
        if (i >= 8064) break;
        int S, off, o, tb;
        if (i < 576)       { S = S0; off = SMF_D0; o = i;        tb = 0;  }
        else if (i < 2880) { S = S1; off = SMF_D1; o = i - 576;  tb = 24; }
        else               { S = S2; off = SMF_D2; o = i - 2880; tb = 72; }
        int oy = o / S, ox = o % S;
        int y0 = s_di[tb + oy];  float wy = s_dw[tb + oy];
        int x0 = s_di[tb + ox];  float wx = s_dw[tb + ox];
        int r0 = y0 * WW, r1 = min(y0 + 1, HH - 1) * WW;
        int x1 = min(x0 + 1, WW - 1);
        float v00 = sy[r0 + x0], v01 = sy[r0 + x1];
        float v10 = sy[r1 + x0], v11 = sy[r1 + x1];
        sm[off + o] = (v00*(1.f-wx) + v01*wx)*(1.f-wy) + (v10*(1.f-wx) + v11*wx)*wy;
    }
    __syncthreads();

    // 3) fused edges + DoG + combine -> zh/zl (2x2 quad per thread)
    float dC = g_dogk[c*3+0], dE = g_dogk[c*3+1], dX = g_dogk[c*3+2];
    float wf = wfea[c];
    const float* pyr[3] = { sm + SMF_D0, sm + SMF_D1, sm + SMF_D2 };
    size_t gbase = (size_t)bc * HWP;
    uint32_t* zh2 = (uint32_t*)(g_zh + gbase);
    uint32_t* zl2 = (uint32_t*)(g_zl + gbase);

#pragma unroll
    for (int k = 0; k < 5; k++) {
        int j = k * PT + t;                 // quad index 0..2303
        if (j >= 2304) break;
        int qh = j / 48, qw = j % 48;
        int h = 2 * qh, w = 2 * qw;

        // ---- 4x4 window for the quad's DoG ----
        float Wd[4][4];
        bool wl = w > 0, wr2 = w < WW - 2;
#pragma unroll
        for (int r = 0; r < 4; r++) {
            int hr = h - 1 + r;
            if (hr >= 0 && hr < HH) {
                const float* rowp = sy + hr * WW;
                float2 m = *(const float2*)(rowp + w);
                Wd[r][1] = m.x; Wd[r][2] = m.y;
                Wd[r][0] = wl  ? rowp[w - 1] : 0.f;
                Wd[r][3] = wr2 ? rowp[w + 2] : 0.f;
            } else {
                Wd[r][0] = Wd[r][1] = Wd[r][2] = Wd[r][3] = 0.f;
            }
        }
        float yc[2][2] = { { Wd[1][1], Wd[1][2] }, { Wd[2][1], Wd[2][2] } };
        float dog[2][2];
#pragma unroll
        for (int r = 0; r < 2; r++)
#pragma unroll
            for (int cc2 = 0; cc2 < 2; cc2++) {
                dog[r][cc2] = dC * Wd[1+r][1+cc2]
                    + dE * (Wd[r][1+cc2] + Wd[2+r][1+cc2] + Wd[1+r][cc2] + Wd[1+r][2+cc2])
                    + dX * (Wd[r][cc2] + Wd[r][2+cc2] + Wd[2+r][cc2] + Wd[2+r][2+cc2]);
            }

        // ---- multi-scale edges via shared 3x3 tap grid per scale ----
        float e[2][2][3];
#pragma unroll
        for (int s = 0; s < 3; s++) {
            const int S = (s == 0) ? S0 : (s == 1) ? S1 : S2;
            const float* p = pyr[s];
            int ya = s_ui[s][h];     float wya = s_uw[s][h];
            int yb = s_ui[s][h+1];   float wyb = s_uw[s][h+1];
            int xa = s_ui[s][w];     float wxa = s_uw[s][w];
            int xb = s_ui[s][w+1];   float wxb = s_uw[s][w+1];
            int dy = yb - ya, dx = xb - xa;      // in {0,1}

            int r0 = ya * S;
            int r1 = min(ya + 1, S - 1) * S;
            int r2 = min(ya + 2, S - 1) * S;
            int c0 = xa;
            int c1 = min(xa + 1, S - 1);
            int c2 = min(xa + 2, S - 1);
            float T[3][3];
            T[0][0] = p[r0+c0]; T[0][1] = p[r0+c1]; T[0][2] = p[r0+c2];
            T[1][0] = p[r1+c0]; T[1][1] = p[r1+c1]; T[1][2] = p[r1+c2];
            T[2][0] = p[r2+c0]; T[2][1] = p[r2+c1]; T[2][2] = p[r2+c2];

#pragma unroll
            for (int r = 0; r < 2; r++) {
                int ri = (r == 0) ? 0 : dy;
                float wy = (r == 0) ? wya : wyb;
#pragma unroll
                for (int cc2 = 0; cc2 < 2; cc2++) {
                    int ci = (cc2 == 0) ? 0 : dx;
                    float wx = (cc2 == 0) ? wxa : wxb;
                    float top = T[ri][ci]   * (1.f - wx) + T[ri][ci+1]   * wx;
                    float bot = T[ri+1][ci] * (1.f - wx) + T[ri+1][ci+1] * wx;
                    float up = top * (1.f - wy) + bot * wy;
                    e[r][cc2][s] = fabsf(yc[r][cc2] - up);
                }
            }
        }

        // ---- combine + bf16 split stores (two rows) ----
#pragma unroll
        for (int r = 0; r < 2; r++) {
            float v0, v1;
            {
                float* ee = e[r][0];
                float we = (fabsf(ee[0]-ee[1]) + fabsf(ee[0]-ee[2])
                          + fabsf(ee[1]-ee[2])) * (1.f/3.f);
                v0 = 3.f*yc[r][0] + wf*we + dog[r][0];
            }
            {
                float* ee = e[r][1];
                float we = (fabsf(ee[0]-ee[1]) + fabsf(ee[0]-ee[2])
                          + fabsf(ee[1]-ee[2])) * (1.f/3.f);
                v1 = 3.f*yc[r][1] + wf*we + dog[r][1];
            }
            __nv_bfloat16 h0 = __float2bfloat16(v0);
            __nv_bfloat16 h1 = __float2bfloat16(v1);
            __nv_bfloat16 l0 = __float2bfloat16(v0 - __bfloat162float(h0));
            __nv_bfloat16 l1 = __float2bfloat16(v1 - __bfloat162float(h1));
            int idx = (h + r) * 48 + qw;
            zh2[idx] = ((uint32_t)__bfloat16_as_ushort(h1) << 16)
                     |  (uint32_t)__bfloat16_as_ushort(h0);
            zl2[idx] = ((uint32_t)__bfloat16_as_ushort(l1) << 16)
                     |  (uint32_t)__bfloat16_as_ushort(l0);
        }
    }
}

// ===========================================================================
// K4: HMMA split-bf16 GEMM (2-stage) — product-major MMA order to break
//     accumulator dependency chains (same-acc separation 2 -> 8 MMAs).
// ===========================================================================
#define ABUF_SZ 10240
#define BUF_STRIDE 36864            // 2*10240 + 2*8192
#define GEMM_SMEM (2*BUF_STRIDE)    // 73728

__global__ void __launch_bounds__(256, 2) k_gemm_mma(
        const float* __restrict__ skip, float* __restrict__ out) {
    extern __shared__ char smem_raw[];
    uint32_t sb = smem_u32(smem_raw);

    int t = threadIdx.x, wid = t >> 5, lane = t & 31;
    int wm = wid & 1, wn = wid >> 1;
    int b = blockIdx.z, co0 = blockIdx.y * 128, n0 = blockIdx.x * 128;

    const __nv_bfloat16* whlo[2] = { g_wh, g_wl };
    const __nv_bfloat16* zhlo[2] = { g_zh, g_zl };

    auto load_chunk = [&](int kc, int d) {
        uint32_t base = sb + d * BUF_STRIDE;
#pragma unroll
        for (int j = 0; j < 4; j++) {            // A
            int idx = j * 256 + t;
            int hl = idx >> 9, rem = idx & 511;
            int row = rem >> 2, c = rem & 3;
            const __nv_bfloat16* src = whlo[hl] + (co0 + row) * CC + kc * 32 + c * 8;
            CP16(base + hl * ABUF_SZ + row * 80 + c * 16, src);
        }
#pragma unroll
        for (int j = 0; j < 4; j++) {            // B
            int idx = j * 256 + t;
            int hl = idx >> 9, rem = idx & 511;
            int row = rem >> 4, c = rem & 15;
            const __nv_bfloat16* src = zhlo[hl]
                + (size_t)(b * CC + kc * 32 + row) * HWP + n0 + c * 8;
            CP16(base + 2 * ABUF_SZ + hl * 8192 + row * 256
                 + (uint32_t)((c ^ (row & 7)) << 4), src);
        }
    };

    float acc[4][4][4];
#pragma unroll
    for (int i = 0; i < 4; i++)
#pragma unroll
        for (int j = 0; j < 4; j++)
#pragma unroll
            for (int k = 0; k < 4; k++) acc[i][j][k] = 0.f;

    int lt = lane >> 3;
    int lrA = (lane & 7) + ((lt & 1) << 3);
    int lcA = (lt >> 1) << 4;
    int lkB = (lane & 7) + ((lt & 1) << 3);
    int lnB = (lt >> 1) << 3;

    load_chunk(0, 0);
    CP_COMMIT();

    for (int kc = 0; kc < 8; kc++) {
        int d = kc & 1;
        if (kc + 1 < 8) { load_chunk(kc + 1, d ^ 1); CP_COMMIT(); CP_WAIT1(); }
        else           { CP_WAIT0(); }
        __syncthreads();

        uint32_t abase = sb + d * BUF_STRIDE;
        uint32_t bbase = abase + 2 * ABUF_SZ;

#pragma unroll
        for (int ks = 0; ks < 2; ks++) {
            uint32_t ah[4][4], al[4][4];
#pragma unroll
            for (int mi = 0; mi < 4; mi++) {
                uint32_t arow = (uint32_t)(wm * 64 + mi * 16 + lrA);
                ldsm_x4(ah[mi], abase + arow * 80 + ks * 32 + lcA);
                ldsm_x4(al[mi], abase + ABUF_SZ + arow * 80 + ks * 32 + lcA);
            }
#pragma unroll
            for (int np = 0; np < 2; np++) {
                uint32_t krow = (uint32_t)(ks * 16 + lkB);
                uint32_t nb   = (uint32_t)(wn * 32 + np * 16 + lnB);
                uint32_t chunk = nb >> 3;
                uint32_t swz = (chunk ^ (krow & 7)) << 4;
                uint32_t bh[4], bl[4];
                ldsm_x4_t(bh, bbase + krow * 256 + swz);
                ldsm_x4_t(bl, bbase + 8192 + krow * 256 + swz);
                // product-major: each acc written once per 8-MMA block
#pragma unroll
                for (int mi = 0; mi < 4; mi++) {
                    mma_bf16(acc[mi][np*2+0], ah[mi], bh + 0);
                    mma_bf16(acc[mi][np*2+1], ah[mi], bh + 2);
                }
#pragma unroll
                for (int mi = 0; mi < 4; mi++) {
                    mma_bf16(acc[mi][np*2+0], ah[mi], bl + 0);
                    mma_bf16(acc[mi][np*2+1], ah[mi], bl + 2);
                }
#pragma unroll
                for (int mi = 0; mi < 4; mi++) {
                    mma_bf16(acc[mi][np*2+0], al[mi], bh + 0);
                    mma_bf16(acc[mi][np*2+1], al[mi], bh + 2);
                }
            }
        }
        __syncthreads();
    }

    int er = lane >> 2, ec = (lane & 3) * 2;
#pragma unroll
    for (int mi = 0; mi < 4; mi++) {
#pragma unroll
        for (int ni = 0; ni < 4; ni++) {
            int row = co0 + wm * 64 + mi * 16 + er;
            int col = n0 + wn * 32 + ni * 8 + ec;
            size_t g0 = (size_t)(b * CC + row) * HWP + col;
            size_t g1 = g0 + 8 * HWP;
            float2 s0 = *(const float2*)(skip + g0);
            float2 s1 = *(const float2*)(skip + g1);
            float2 o0 = make_float2(acc[mi][ni][0] + s0.x, acc[mi][ni][1] + s0.y);
            float2 o1 = make_float2(acc[mi][ni][2] + s1.x, acc[mi][ni][3] + s1.y);
            *(float2*)(out + g0) = o0;
            *(float2*)(out + g1) = o1;
        }
    }
}

// ===========================================================================
extern "C" void kernel_launch(void* const* d_in, const int* in_sizes, int n_in,
                              void* d_out, int out_size) {
    const float* skip   = (const float*)d_in[0];
    const float* dec    = (const float*)d_in[1];
    const float* w_fea  = (const float*)d_in[2];
    const float* sigma1 = (const float*)d_in[3];
    const float* sigma2 = (const float*)d_in[4];
    const float* mixerw = (const float*)d_in[5];
    float* out = (float*)d_out;

    k_params<<<1, CC>>>(sigma1, sigma2);
    k_wsplit<<<CC*CC/256, 256>>>(mixerw);

    cudaFuncSetAttribute(k_plane, cudaFuncAttributeMaxDynamicSharedMemorySize,
                         PLANE_SMEM);
    k_plane<<<BB*CC, PT, PLANE_SMEM>>>((const float4*)dec, (const float4*)skip,
                                       w_fea);

    cudaFuncSetAttribute(k_gemm_mma, cudaFuncAttributeMaxDynamicSharedMemorySize,
                         GEMM_SMEM);
    dim3 grid(HWP / 128, CC / 128, BB);
    k_gemm_mma<<<grid, 256, GEMM_SMEM>>>(skip, out);
}

// round 8
// speedup vs baseline: 1.0642x; 1.0642x over previous
#include <cuda_runtime.h>
#include <cuda_bf16.h>
#include <math.h>
#include <stdint.h>

// ---- problem constants ----
#define BB 16
#define CC 256
#define HH 96
#define WW 96
#define HWP (HH*WW)                 // 9216
#define NELEM (BB*CC*HWP)           // 37748736
#define S0 24
#define S1 48
#define S2 72

// ---- scratch (device globals: allocation-free rule) ----
__device__ __nv_bfloat16 g_zh[NELEM];
__device__ __nv_bfloat16 g_zl[NELEM];
__device__ __nv_bfloat16 g_wh[CC*CC];
__device__ __nv_bfloat16 g_wl[CC*CC];
__device__ float g_dogk[CC*3];

// ===========================================================================
// PTX helpers
// ===========================================================================
__device__ __forceinline__ uint32_t smem_u32(const void* p) {
    uint32_t a;
    asm("{ .reg .u64 t; cvta.to.shared.u64 t, %1; cvt.u32.u64 %0, t; }"
        : "=r"(a) : "l"(p));
    return a;
}
#define CP16(dst, src) asm volatile( \
    "cp.async.cg.shared.global [%0], [%1], 16;" :: "r"(dst), "l"(src) : "memory")
#define CP_COMMIT() asm volatile("cp.async.commit_group;" ::: "memory")
#define CP_WAIT1() asm volatile("cp.async.wait_group 1;" ::: "memory")
#define CP_WAIT0() asm volatile("cp.async.wait_group 0;" ::: "memory")

__device__ __forceinline__ void ldsm_x4(uint32_t* r, uint32_t addr) {
    asm volatile("ldmatrix.sync.aligned.m8n8.x4.shared.b16 {%0,%1,%2,%3}, [%4];"
                 : "=r"(r[0]), "=r"(r[1]), "=r"(r[2]), "=r"(r[3]) : "r"(addr));
}
__device__ __forceinline__ void ldsm_x4_t(uint32_t* r, uint32_t addr) {
    asm volatile("ldmatrix.sync.aligned.m8n8.x4.trans.shared.b16 {%0,%1,%2,%3}, [%4];"
                 : "=r"(r[0]), "=r"(r[1]), "=r"(r[2]), "=r"(r[3]) : "r"(addr));
}
__device__ __forceinline__ void mma_bf16(float* c, const uint32_t* a, const uint32_t* b) {
    asm volatile(
        "mma.sync.aligned.m16n8k16.row.col.f32.bf16.bf16.f32 "
        "{%0,%1,%2,%3}, {%4,%5,%6,%7}, {%8,%9}, {%0,%1,%2,%3};"
        : "+f"(c[0]), "+f"(c[1]), "+f"(c[2]), "+f"(c[3])
        : "r"(a[0]), "r"(a[1]), "r"(a[2]), "r"(a[3]), "r"(b[0]), "r"(b[1]));
}

// ===========================================================================
// K0: per-channel DoG difference-kernel coefficients
// ===========================================================================
__global__ void k_params(const float* __restrict__ s1r, const float* __restrict__ s2r) {
    int c = threadIdx.x;
    float s1 = 2.f / (1.f + expf(-s1r[c]));
    float s2 = 2.f / (1.f + expf(-s2r[c]));
    float e1 = expf(-1.f / (2.f * s1 * s1)); float q1 = expf(-1.f / (s1 * s1));
    float e2 = expf(-1.f / (2.f * s2 * s2)); float q2 = expf(-1.f / (s2 * s2));
    float n1 = 1.f + 4.f * e1 + 4.f * q1;
    float n2 = 1.f + 4.f * e2 + 4.f * q2;
    g_dogk[c*3+0] = 1.f/n1 - 1.f/n2;
    g_dogk[c*3+1] = e1/n1 - e2/n2;
    g_dogk[c*3+2] = q1/n1 - q2/n2;
}

// K0b: split mixer weight into bf16 hi/lo
__global__ void k_wsplit(const float* __restrict__ w) {
    int i = blockIdx.x * 256 + threadIdx.x;
    float v = w[i];
    __nv_bfloat16 h = __float2bfloat16(v);
    g_wh[i] = h;
    g_wl[i] = __float2bfloat16(v - __bfloat162float(h));
}

// ===========================================================================
// K1: fused per-plane elementwise chain. One CTA / (b,c) plane, 512 threads.
//   Phase 3: pixel-pair per thread; DoG middle taps via conflict-free LDS.64.
// ===========================================================================
#define SMF_Y  0
#define SMF_D0 9216
#define SMF_D1 (9216+576)
#define SMF_D2 (9216+2880)
#define PLANE_SMEM ((9216+8064)*4)   // 69120 B dynamic
#define PT 512

__global__ void __launch_bounds__(PT) k_plane(const float4* __restrict__ dec,
                                              const float4* __restrict__ skip,
                                              const float* __restrict__ wfea) {
    extern __shared__ float sm[];
    __shared__ int   s_ui[3][96];
    __shared__ float s_uw[3][96];
    __shared__ int   s_di[144];
    __shared__ float s_dw[144];

    int bc = blockIdx.x;
    int c  = bc % CC;
    int t  = threadIdx.x;

    // 0) fill coordinate tables
    if (t < 288) {
        int s = t / 96, o = t % 96;
        float scl = (s == 0) ? (S0/96.f) : (s == 1) ? (S1/96.f) : (S2/96.f);
        int S = (s == 0) ? S0 : (s == 1) ? S1 : S2;
        float f = fmaxf((o + 0.5f) * scl - 0.5f, 0.f);
        int i0 = (int)f;
        if (i0 > S - 1) i0 = S - 1;
        s_ui[s][o] = i0;
        s_uw[s][o] = f - (float)i0;
    } else if (t < 432) {
        int u = t - 288;
        int s = (u < 24) ? 0 : (u < 72) ? 1 : 2;
        int o = (s == 0) ? u : (s == 1) ? u - 24 : u - 72;
        float sf = (s == 0) ? (96.f/S0) : (s == 1) ? (96.f/S1) : (96.f/S2);
        float f = fmaxf((o + 0.5f) * sf - 0.5f, 0.f);
        int i0 = (int)f;
        s_di[u] = i0;
        s_dw[u] = f - (float)i0;
    }

    // 1) y = dec + skip into smem
    const float4* dp = dec  + (size_t)bc * (HWP/4);
    const float4* sp = skip + (size_t)bc * (HWP/4);
    float4* y4 = (float4*)(sm + SMF_Y);
#pragma unroll
    for (int k = 0; k < 5; k++) {
        int i = k * PT + t;
        if (i < HWP/4) {
            float4 a = dp[i], b = sp[i];
            y4[i] = make_float4(a.x + b.x, a.y + b.y, a.z + b.z, a.w + b.w);
        }
    }
    __syncthreads();

    const float* sy = sm + SMF_Y;

    // 2) three bilinear downsamples into smem (8064 outputs) via tables
#pragma unroll
    for (int k = 0; k < 16; k++) {
        int i = k * PT + t;
        if (i >= 8064) break;
        int S, off, o, tb;
        if (i < 576)       { S = S0; off = SMF_D0; o = i;        tb = 0;  }
        else if (i < 2880) { S = S1; off = SMF_D1; o = i - 576;  tb = 24; }
        else               { S = S2; off = SMF_D2; o = i - 2880; tb = 72; }
        int oy = o / S, ox = o % S;
        int y0 = s_di[tb + oy];  float wy = s_dw[tb + oy];
        int x0 = s_di[tb + ox];  float wx = s_dw[tb + ox];
        int r0 = y0 * WW, r1 = min(y0 + 1, HH - 1) * WW;
        int x1 = min(x0 + 1, WW - 1);
        float v00 = sy[r0 + x0], v01 = sy[r0 + x1];
        float v10 = sy[r1 + x0], v11 = sy[r1 + x1];
        sm[off + o] = (v00*(1.f-wx) + v01*wx)*(1.f-wy) + (v10*(1.f-wx) + v11*wx)*wy;
    }
    __syncthreads();

    // 3) fused edges + DoG + combine -> zh/zl (2 px per thread, LDS.64 taps)
    float dC = g_dogk[c*3+0], dE = g_dogk[c*3+1], dX = g_dogk[c*3+2];
    float wf = wfea[c];
    const float* pyr[3] = { sm + SMF_D0, sm + SMF_D1, sm + SMF_D2 };
    size_t gbase = (size_t)bc * HWP;
    uint32_t* zh2 = (uint32_t*)(g_zh + gbase);
    uint32_t* zl2 = (uint32_t*)(g_zl + gbase);

#pragma unroll
    for (int k = 0; k < 9; k++) {
        int j = k * PT + t;          // pair index; i = 2j, both pixels same row
        int i = 2 * j;
        int h = i / WW, w = i % WW;  // w even, w+1 < 96 always

        // ---- DoG: 3 rows x 4 cols; middle pair via aligned float2 ----
        float a[3][4];
        bool hu = h > 0, hd = h < HH - 1, wl = w > 0, wr2 = w < WW - 2;
#pragma unroll
        for (int r = 0; r < 3; r++) {
            int hr = h - 1 + r;
            bool hv = (r == 1) | (r == 0 ? hu : hd);
            if (hv) {
                const float* rowp = sy + hr * WW;
                float2 m = *(const float2*)(rowp + w);   // w even: 8B-aligned
                a[r][1] = m.x; a[r][2] = m.y;
                a[r][0] = wl  ? rowp[w - 1] : 0.f;
                a[r][3] = wr2 ? rowp[w + 2] : 0.f;
            } else {
                a[r][0] = a[r][1] = a[r][2] = a[r][3] = 0.f;
            }
        }
        float yc0 = a[1][1], yc1 = a[1][2];
        float dog0 = dC*yc0 + dE*(a[0][1]+a[2][1]+a[1][0]+a[1][2])
                   + dX*(a[0][0]+a[0][2]+a[2][0]+a[2][2]);
        float dog1 = dC*yc1 + dE*(a[0][2]+a[2][2]+a[1][1]+a[1][3])
                   + dX*(a[0][1]+a[0][3]+a[2][1]+a[2][3]);

        // ---- multi-scale edges via tables ----
        float e0[3], e1[3];
#pragma unroll
        for (int s = 0; s < 3; s++) {
            const int S = (s == 0) ? S0 : (s == 1) ? S1 : S2;
            int y0 = s_ui[s][h]; float wy = s_uw[s][h];
            int r0 = y0 * S, r1 = min(y0 + 1, S - 1) * S;
            const float* p = pyr[s];
            // pixel 0
            int xa = s_ui[s][w]; float wxa = s_uw[s][w];
            int xa1 = min(xa + 1, S - 1);
            float u0 = (p[r0+xa]*(1.f-wxa) + p[r0+xa1]*wxa)*(1.f-wy)
                     + (p[r1+xa]*(1.f-wxa) + p[r1+xa1]*wxa)*wy;
            // pixel 1
            int xb = s_ui[s][w+1]; float wxb = s_uw[s][w+1];
            int xb1 = min(xb + 1, S - 1);
            float u1 = (p[r0+xb]*(1.f-wxb) + p[r0+xb1]*wxb)*(1.f-wy)
                     + (p[r1+xb]*(1.f-wxb) + p[r1+xb1]*wxb)*wy;
            e0[s] = fabsf(yc0 - u0);
            e1[s] = fabsf(yc1 - u1);
        }
        float we0 = (fabsf(e0[0]-e0[1]) + fabsf(e0[0]-e0[2]) + fabsf(e0[1]-e0[2]))
                    * (1.f/3.f);
        float we1 = (fabsf(e1[0]-e1[1]) + fabsf(e1[0]-e1[2]) + fabsf(e1[1]-e1[2]))
                    * (1.f/3.f);

        float v0 = 3.f*yc0 + wf*we0 + dog0;
        float v1 = 3.f*yc1 + wf*we1 + dog1;
        __nv_bfloat16 h0 = __float2bfloat16(v0);
        __nv_bfloat16 h1 = __float2bfloat16(v1);
        __nv_bfloat16 l0 = __float2bfloat16(v0 - __bfloat162float(h0));
        __nv_bfloat16 l1 = __float2bfloat16(v1 - __bfloat162float(h1));
        zh2[j] = ((uint32_t)__bfloat16_as_ushort(h1) << 16)
               |  (uint32_t)__bfloat16_as_ushort(h0);
        zl2[j] = ((uint32_t)__bfloat16_as_ushort(l1) << 16)
               |  (uint32_t)__bfloat16_as_ushort(l0);
    }
}

// ===========================================================================
// K4: HMMA split-bf16 GEMM (exact R4/R6 config, measured 175.4us)
// ===========================================================================
#define ABUF_SZ 10240
#define BUF_STRIDE 36864            // 2*10240 + 2*8192
#define GEMM_SMEM (2*BUF_STRIDE)    // 73728

__global__ void __launch_bounds__(256, 2) k_gemm_mma(
        const float* __restrict__ skip, float* __restrict__ out) {
    extern __shared__ char smem_raw[];
    uint32_t sb = smem_u32(smem_raw);

    int t = threadIdx.x, wid = t >> 5, lane = t & 31;
    int wm = wid & 1, wn = wid >> 1;
    int b = blockIdx.z, co0 = blockIdx.y * 128, n0 = blockIdx.x * 128;

    const __nv_bfloat16* whlo[2] = { g_wh, g_wl };
    const __nv_bfloat16* zhlo[2] = { g_zh, g_zl };

    auto load_chunk = [&](int kc, int d) {
        uint32_t base = sb + d * BUF_STRIDE;
#pragma unroll
        for (int j = 0; j < 4; j++) {            // A
            int idx = j * 256 + t;
            int hl = idx >> 9, rem = idx & 511;
            int row = rem >> 2, c = rem & 3;
            const __nv_bfloat16* src = whlo[hl] + (co0 + row) * CC + kc * 32 + c * 8;
            CP16(base + hl * ABUF_SZ + row * 80 + c * 16, src);
        }
#pragma unroll
        for (int j = 0; j < 4; j++) {            // B
            int idx = j * 256 + t;
            int hl = idx >> 9, rem = idx & 511;
            int row = rem >> 4, c = rem & 15;
            const __nv_bfloat16* src = zhlo[hl]
                + (size_t)(b * CC + kc * 32 + row) * HWP + n0 + c * 8;
            CP16(base + 2 * ABUF_SZ + hl * 8192 + row * 256
                 + (uint32_t)((c ^ (row & 7)) << 4), src);
        }
    };

    float acc[4][4][4];
#pragma unroll
    for (int i = 0; i < 4; i++)
#pragma unroll
        for (int j = 0; j < 4; j++)
#pragma unroll
            for (int k = 0; k < 4; k++) acc[i][j][k] = 0.f;

    int lt = lane >> 3;
    int lrA = (lane & 7) + ((lt & 1) << 3);
    int lcA = (lt >> 1) << 4;
    int lkB = (lane & 7) + ((lt & 1) << 3);
    int lnB = (lt >> 1) << 3;

    load_chunk(0, 0);
    CP_COMMIT();

    for (int kc = 0; kc < 8; kc++) {
        int d = kc & 1;
        if (kc + 1 < 8) { load_chunk(kc + 1, d ^ 1); CP_COMMIT(); CP_WAIT1(); }
        else           { CP_WAIT0(); }
        __syncthreads();

        uint32_t abase = sb + d * BUF_STRIDE;
        uint32_t bbase = abase + 2 * ABUF_SZ;

#pragma unroll
        for (int ks = 0; ks < 2; ks++) {
            uint32_t ah[4][4], al[4][4];
#pragma unroll
            for (int mi = 0; mi < 4; mi++) {
                uint32_t arow = (uint32_t)(wm * 64 + mi * 16 + lrA);
                ldsm_x4(ah[mi], abase + arow * 80 + ks * 32 + lcA);
                ldsm_x4(al[mi], abase + ABUF_SZ + arow * 80 + ks * 32 + lcA);
            }
#pragma unroll
            for (int np = 0; np < 2; np++) {
                uint32_t krow = (uint32_t)(ks * 16 + lkB);
                uint32_t nb   = (uint32_t)(wn * 32 + np * 16 + lnB);
                uint32_t chunk = nb >> 3;
                uint32_t swz = (chunk ^ (krow & 7)) << 4;
                uint32_t bh[4], bl[4];
                ldsm_x4_t(bh, bbase + krow * 256 + swz);
                ldsm_x4_t(bl, bbase + 8192 + krow * 256 + swz);
#pragma unroll
                for (int mi = 0; mi < 4; mi++) {
                    mma_bf16(acc[mi][np*2+0], ah[mi], bh + 0);
                    mma_bf16(acc[mi][np*2+1], ah[mi], bh + 2);
                    mma_bf16(acc[mi][np*2+0], ah[mi], bl + 0);
                    mma_bf16(acc[mi][np*2+1], ah[mi], bl + 2);
                    mma_bf16(acc[mi][np*2+0], al[mi], bh + 0);
                    mma_bf16(acc[mi][np*2+1], al[mi], bh + 2);
                }
            }
        }
        __syncthreads();
    }

    int er = lane >> 2, ec = (lane & 3) * 2;
#pragma unroll
    for (int mi = 0; mi < 4; mi++) {
#pragma unroll
        for (int ni = 0; ni < 4; ni++) {
            int row = co0 + wm * 64 + mi * 16 + er;
            int col = n0 + wn * 32 + ni * 8 + ec;
            size_t g0 = (size_t)(b * CC + row) * HWP + col;
            size_t g1 = g0 + 8 * HWP;
            float2 s0 = *(const float2*)(skip + g0);
            float2 s1 = *(const float2*)(skip + g1);
            float2 o0 = make_float2(acc[mi][ni][0] + s0.x, acc[mi][ni][1] + s0.y);
            float2 o1 = make_float2(acc[mi][ni][2] + s1.x, acc[mi][ni][3] + s1.y);
            *(float2*)(out + g0) = o0;
            *(float2*)(out + g1) = o1;
        }
    }
}

// ===========================================================================
extern "C" void kernel_launch(void* const* d_in, const int* in_sizes, int n_in,
                              void* d_out, int out_size) {
    const float* skip   = (const float*)d_in[0];
    const float* dec    = (const float*)d_in[1];
    const float* w_fea  = (const float*)d_in[2];
    const float* sigma1 = (const float*)d_in[3];
    const float* sigma2 = (const float*)d_in[4];
    const float* mixerw = (const float*)d_in[5];
    float* out = (float*)d_out;

    k_params<<<1, CC>>>(sigma1, sigma2);
    k_wsplit<<<CC*CC/256, 256>>>(mixerw);

    cudaFuncSetAttribute(k_plane, cudaFuncAttributeMaxDynamicSharedMemorySize,
                         PLANE_SMEM);
    k_plane<<<BB*CC, PT, PLANE_SMEM>>>((const float4*)dec, (const float4*)skip,
                                       w_fea);

    cudaFuncSetAttribute(k_gemm_mma, cudaFuncAttributeMaxDynamicSharedMemorySize,
                         GEMM_SMEM);
    dim3 grid(HWP / 128, CC / 128, BB);
    k_gemm_mma<<<grid, 256, GEMM_SMEM>>>(skip, out);
}

// round 10
// speedup vs baseline: 1.1137x; 1.0465x over previous
#include <cuda_runtime.h>
#include <cuda_bf16.h>
#include <math.h>
#include <stdint.h>

// ---- problem constants ----
#define BB 16
#define CC 256
#define HH 96
#define WW 96
#define HWP (HH*WW)                 // 9216
#define NELEM (BB*CC*HWP)           // 37748736
#define S0 24
#define S1 48
#define S2 72

// ---- scratch (device globals: allocation-free rule) ----
__device__ __nv_bfloat16 g_zh[NELEM];
__device__ __nv_bfloat16 g_zl[NELEM];
__device__ __nv_bfloat16 g_wh[CC*CC];
__device__ __nv_bfloat16 g_wl[CC*CC];
__device__ float g_dogk[CC*3];

// ===========================================================================
// PTX helpers
// ===========================================================================
__device__ __forceinline__ uint32_t smem_u32(const void* p) {
    uint32_t a;
    asm("{ .reg .u64 t; cvta.to.shared.u64 t, %1; cvt.u32.u64 %0, t; }"
        : "=r"(a) : "l"(p));
    return a;
}
#define CP16(dst, src) asm volatile( \
    "cp.async.cg.shared.global [%0], [%1], 16;" :: "r"(dst), "l"(src) : "memory")
#define CP_COMMIT() asm volatile("cp.async.commit_group;" ::: "memory")
#define CP_WAIT1() asm volatile("cp.async.wait_group 1;" ::: "memory")
#define CP_WAIT0() asm volatile("cp.async.wait_group 0;" ::: "memory")

__device__ __forceinline__ void ldsm_x4(uint32_t* r, uint32_t addr) {
    asm volatile("ldmatrix.sync.aligned.m8n8.x4.shared.b16 {%0,%1,%2,%3}, [%4];"
                 : "=r"(r[0]), "=r"(r[1]), "=r"(r[2]), "=r"(r[3]) : "r"(addr));
}
__device__ __forceinline__ void ldsm_x4_t(uint32_t* r, uint32_t addr) {
    asm volatile("ldmatrix.sync.aligned.m8n8.x4.trans.shared.b16 {%0,%1,%2,%3}, [%4];"
                 : "=r"(r[0]), "=r"(r[1]), "=r"(r[2]), "=r"(r[3]) : "r"(addr));
}
__device__ __forceinline__ void mma_bf16(float* c, const uint32_t* a, const uint32_t* b) {
    asm volatile(
        "mma.sync.aligned.m16n8k16.row.col.f32.bf16.bf16.f32 "
        "{%0,%1,%2,%3}, {%4,%5,%6,%7}, {%8,%9}, {%0,%1,%2,%3};"
        : "+f"(c[0]), "+f"(c[1]), "+f"(c[2]), "+f"(c[3])
        : "r"(a[0]), "r"(a[1]), "r"(a[2]), "r"(a[3]), "r"(b[0]), "r"(b[1]));
}

// ===========================================================================
// K0: per-channel DoG difference-kernel coefficients
// ===========================================================================
__global__ void k_params(const float* __restrict__ s1r, const float* __restrict__ s2r) {
    int c = threadIdx.x;
    float s1 = 2.f / (1.f + expf(-s1r[c]));
    float s2 = 2.f / (1.f + expf(-s2r[c]));
    float e1 = expf(-1.f / (2.f * s1 * s1)); float q1 = expf(-1.f / (s1 * s1));
    float e2 = expf(-1.f / (2.f * s2 * s2)); float q2 = expf(-1.f / (s2 * s2));
    float n1 = 1.f + 4.f * e1 + 4.f * q1;
    float n2 = 1.f + 4.f * e2 + 4.f * q2;
    g_dogk[c*3+0] = 1.f/n1 - 1.f/n2;
    g_dogk[c*3+1] = e1/n1 - e2/n2;
    g_dogk[c*3+2] = q1/n1 - q2/n2;
}

// K0b: split mixer weight into bf16 hi/lo
__global__ void k_wsplit(const float* __restrict__ w) {
    int i = blockIdx.x * 256 + threadIdx.x;
    float v = w[i];
    __nv_bfloat16 h = __float2bfloat16(v);
    g_wh[i] = h;
    g_wl[i] = __float2bfloat16(v - __bfloat162float(h));
}

// select T[xi] and T[xi+1] from a 5-register grid, xi in 0..3 (FSEL chains)
__device__ __forceinline__ void sel2of5(const float T[5], int xi,
                                        float& lo, float& hi) {
    float a = (xi == 1) ? T[1] : T[0];
    a = (xi == 2) ? T[2] : a;
    a = (xi == 3) ? T[3] : a;
    float b = (xi == 1) ? T[2] : T[1];
    b = (xi == 2) ? T[3] : b;
    b = (xi == 3) ? T[4] : b;
    lo = a; hi = b;
}

// ===========================================================================
// K1: fused per-plane elementwise chain. One CTA / (b,c) plane, 512 threads.
//   Phase 3: 4-pixel strips; 5-tap shared grids (max col span over 4px = 3).
// ===========================================================================
#define SMF_Y  0
#define SMF_D0 9216
#define SMF_D1 (9216+576)
#define SMF_D2 (9216+2880)
#define PLANE_SMEM ((9216+8064)*4)   // 69120 B dynamic
#define PT 512

__global__ void __launch_bounds__(PT) k_plane(const float4* __restrict__ dec,
                                              const float4* __restrict__ skip,
                                              const float* __restrict__ wfea) {
    extern __shared__ float sm[];
    __shared__ int   s_ui[3][96];
    __shared__ float s_uw[3][96];
    __shared__ int   s_di[144];
    __shared__ float s_dw[144];

    int bc = blockIdx.x;
    int c  = bc % CC;
    int t  = threadIdx.x;

    // 0) fill coordinate tables
    if (t < 288) {
        int s = t / 96, o = t % 96;
        float scl = (s == 0) ? (S0/96.f) : (s == 1) ? (S1/96.f) : (S2/96.f);
        int S = (s == 0) ? S0 : (s == 1) ? S1 : S2;
        float f = fmaxf((o + 0.5f) * scl - 0.5f, 0.f);
        int i0 = (int)f;
        if (i0 > S - 1) i0 = S - 1;
        s_ui[s][o] = i0;
        s_uw[s][o] = f - (float)i0;
    } else if (t < 432) {
        int u = t - 288;
        int s = (u < 24) ? 0 : (u < 72) ? 1 : 2;
        int o = (s == 0) ? u : (s == 1) ? u - 24 : u - 72;
        float sf = (s == 0) ? (96.f/S0) : (s == 1) ? (96.f/S1) : (96.f/S2);
        float f = fmaxf((o + 0.5f) * sf - 0.5f, 0.f);
        int i0 = (int)f;
        s_di[u] = i0;
        s_dw[u] = f - (float)i0;
    }

    // 1) y = dec + skip into smem
    const float4* dp = dec  + (size_t)bc * (HWP/4);
    const float4* sp = skip + (size_t)bc * (HWP/4);
    float4* y4 = (float4*)(sm + SMF_Y);
#pragma unroll
    for (int k = 0; k < 5; k++) {
        int i = k * PT + t;
        if (i < HWP/4) {
            float4 a = dp[i], b = sp[i];
            y4[i] = make_float4(a.x + b.x, a.y + b.y, a.z + b.z, a.w + b.w);
        }
    }
    __syncthreads();

    const float* sy = sm + SMF_Y;

    // 2) three bilinear downsamples into smem (8064 outputs) via tables
#pragma unroll
    for (int k = 0; k < 16; k++) {
        int i = k * PT + t;
        if (i >= 8064) break;
        int S, off, o, tb;
        if (i < 576)       { S = S0; off = SMF_D0; o = i;        tb = 0;  }
        else if (i < 2880) { S = S1; off = SMF_D1; o = i - 576;  tb = 24; }
        else               { S = S2; off = SMF_D2; o = i - 2880; tb = 72; }
        int oy = o / S, ox = o % S;
        int y0 = s_di[tb + oy];  float wy = s_dw[tb + oy];
        int x0 = s_di[tb + ox];  float wx = s_dw[tb + ox];
        int r0 = y0 * WW, r1 = min(y0 + 1, HH - 1) * WW;
        int x1 = min(x0 + 1, WW - 1);
        float v00 = sy[r0 + x0], v01 = sy[r0 + x1];
        float v10 = sy[r1 + x0], v11 = sy[r1 + x1];
        sm[off + o] = (v00*(1.f-wx) + v01*wx)*(1.f-wy) + (v10*(1.f-wx) + v11*wx)*wy;
    }
    __syncthreads();

    // 3) fused edges + DoG + combine -> zh/zl: 4-pixel strips
    float dC = g_dogk[c*3+0], dE = g_dogk[c*3+1], dX = g_dogk[c*3+2];
    float wf = wfea[c];
    const float* pyr[3] = { sm + SMF_D0, sm + SMF_D1, sm + SMF_D2 };
    size_t gbase = (size_t)bc * HWP;
    uint2* zh4 = (uint2*)(g_zh + gbase);
    uint2* zl4 = (uint2*)(g_zl + gbase);

#pragma unroll
    for (int k = 0; k < 5; k++) {
        int j = k * PT + t;                 // strip index 0..2303 (24 per row)
        if (j < 2304) {
            int h = j / 24, w = 4 * (j % 24);

            // ---- DoG window: 3 rows x 6 cols (float4 middle + 2 edge taps) ----
            float R[3][6];
            bool wl = w > 0, wr = w < WW - 4;
#pragma unroll
            for (int r = 0; r < 3; r++) {
                int hr = h - 1 + r;
                if (hr >= 0 && hr < HH) {
                    const float* rowp = sy + hr * WW;
                    float4 m = *(const float4*)(rowp + w);   // w%4==0: aligned
                    R[r][1] = m.x; R[r][2] = m.y; R[r][3] = m.z; R[r][4] = m.w;
                    R[r][0] = wl ? rowp[w - 1] : 0.f;
                    R[r][5] = wr ? rowp[w + 4] : 0.f;
                } else {
#pragma unroll
                    for (int q = 0; q < 6; q++) R[r][q] = 0.f;
                }
            }
            float yc[4], dog[4];
#pragma unroll
            for (int px = 0; px < 4; px++) {
                yc[px] = R[1][px + 1];
                dog[px] = dC * R[1][px+1]
                        + dE * (R[0][px+1] + R[2][px+1] + R[1][px] + R[1][px+2])
                        + dX * (R[0][px] + R[0][px+2] + R[2][px] + R[2][px+2]);
            }

            // ---- multi-scale edges: shared 2x5 tap grid per scale ----
            float e[4][3];
#pragma unroll
            for (int s = 0; s < 3; s++) {
                const int S = (s == 0) ? S0 : (s == 1) ? S1 : S2;
                const float* p = pyr[s];
                int y0 = s_ui[s][h]; float wy = s_uw[s][h];
                int r0 = y0 * S, r1 = min(y0 + 1, S - 1) * S;
                int x0 = s_ui[s][w];                   // min source col (monotone)
                int c1 = min(x0 + 1, S - 1);
                int c2 = min(x0 + 2, S - 1);
                int c3 = min(x0 + 3, S - 1);
                int c4 = min(x0 + 4, S - 1);
                float T0[5] = { p[r0+x0], p[r0+c1], p[r0+c2], p[r0+c3], p[r0+c4] };
                float T1[5] = { p[r1+x0], p[r1+c1], p[r1+c2], p[r1+c3], p[r1+c4] };
#pragma unroll
                for (int px = 0; px < 4; px++) {
                    int xi = s_ui[s][w + px] - x0;     // 0..3
                    float wx = s_uw[s][w + px];
                    float t0, t1, b0, b1;
                    sel2of5(T0, xi, t0, t1);
                    sel2of5(T1, xi, b0, b1);
                    float top = t0 + (t1 - t0) * wx;
                    float bot = b0 + (b1 - b0) * wx;
                    float up = top + (bot - top) * wy;
                    e[px][s] = fabsf(yc[px] - up);
                }
            }

            // ---- combine + bf16 split, 8B stores ----
            uint32_t hp[2], lp[2];
#pragma unroll
            for (int half = 0; half < 2; half++) {
                float v0, v1;
                {
                    float* ee = e[half*2];
                    float we = (fabsf(ee[0]-ee[1]) + fabsf(ee[0]-ee[2])
                              + fabsf(ee[1]-ee[2])) * (1.f/3.f);
                    v0 = 3.f*yc[half*2] + wf*we + dog[half*2];
                }
                {
                    float* ee = e[half*2+1];
                    float we = (fabsf(ee[0]-ee[1]) + fabsf(ee[0]-ee[2])
                              + fabsf(ee[1]-ee[2])) * (1.f/3.f);
                    v1 = 3.f*yc[half*2+1] + wf*we + dog[half*2+1];
                }
                __nv_bfloat16 h0 = __float2bfloat16(v0);
                __nv_bfloat16 h1 = __float2bfloat16(v1);
                __nv_bfloat16 l0 = __float2bfloat16(v0 - __bfloat162float(h0));
                __nv_bfloat16 l1 = __float2bfloat16(v1 - __bfloat162float(h1));
                hp[half] = ((uint32_t)__bfloat16_as_ushort(h1) << 16)
                         |  (uint32_t)__bfloat16_as_ushort(h0);
                lp[half] = ((uint32_t)__bfloat16_as_ushort(l1) << 16)
                         |  (uint32_t)__bfloat16_as_ushort(l0);
            }
            zh4[j] = make_uint2(hp[0], hp[1]);
            zl4[j] = make_uint2(lp[0], lp[1]);
        }
    }
}

// ===========================================================================
// K4: HMMA split-bf16 GEMM (exact R4/R6 config, measured ~174us)
// ===========================================================================
#define ABUF_SZ 10240
#define BUF_STRIDE 36864            // 2*10240 + 2*8192
#define GEMM_SMEM (2*BUF_STRIDE)    // 73728

__global__ void __launch_bounds__(256, 2) k_gemm_mma(
        const float* __restrict__ skip, float* __restrict__ out) {
    extern __shared__ char smem_raw[];
    uint32_t sb = smem_u32(smem_raw);

    int t = threadIdx.x, wid = t >> 5, lane = t & 31;
    int wm = wid & 1, wn = wid >> 1;
    int b = blockIdx.z, co0 = blockIdx.y * 128, n0 = blockIdx.x * 128;

    const __nv_bfloat16* whlo[2] = { g_wh, g_wl };
    const __nv_bfloat16* zhlo[2] = { g_zh, g_zl };

    auto load_chunk = [&](int kc, int d) {
        uint32_t base = sb + d * BUF_STRIDE;
#pragma unroll
        for (int j = 0; j < 4; j++) {            // A
            int idx = j * 256 + t;
            int hl = idx >> 9, rem = idx & 511;
            int row = rem >> 2, c = rem & 3;
            const __nv_bfloat16* src = whlo[hl] + (co0 + row) * CC + kc * 32 + c * 8;
            CP16(base + hl * ABUF_SZ + row * 80 + c * 16, src);
        }
#pragma unroll
        for (int j = 0; j < 4; j++) {            // B
            int idx = j * 256 + t;
            int hl = idx >> 9, rem = idx & 511;
            int row = rem >> 4, c = rem & 15;
            const __nv_bfloat16* src = zhlo[hl]
                + (size_t)(b * CC + kc * 32 + row) * HWP + n0 + c * 8;
            CP16(base + 2 * ABUF_SZ + hl * 8192 + row * 256
                 + (uint32_t)((c ^ (row & 7)) << 4), src);
        }
    };

    float acc[4][4][4];
#pragma unroll
    for (int i = 0; i < 4; i++)
#pragma unroll
        for (int j = 0; j < 4; j++)
#pragma unroll
            for (int k = 0; k < 4; k++) acc[i][j][k] = 0.f;

    int lt = lane >> 3;
    int lrA = (lane & 7) + ((lt & 1) << 3);
    int lcA = (lt >> 1) << 4;
    int lkB = (lane & 7) + ((lt & 1) << 3);
    int lnB = (lt >> 1) << 3;

    load_chunk(0, 0);
    CP_COMMIT();

    for (int kc = 0; kc < 8; kc++) {
        int d = kc & 1;
        if (kc + 1 < 8) { load_chunk(kc + 1, d ^ 1); CP_COMMIT(); CP_WAIT1(); }
        else           { CP_WAIT0(); }
        __syncthreads();

        uint32_t abase = sb + d * BUF_STRIDE;
        uint32_t bbase = abase + 2 * ABUF_SZ;

#pragma unroll
        for (int ks = 0; ks < 2; ks++) {
            uint32_t ah[4][4], al[4][4];
#pragma unroll
            for (int mi = 0; mi < 4; mi++) {
                uint32_t arow = (uint32_t)(wm * 64 + mi * 16 + lrA);
                ldsm_x4(ah[mi], abase + arow * 80 + ks * 32 + lcA);
                ldsm_x4(al[mi], abase + ABUF_SZ + arow * 80 + ks * 32 + lcA);
            }
#pragma unroll
            for (int np = 0; np < 2; np++) {
                uint32_t krow = (uint32_t)(ks * 16 + lkB);
                uint32_t nb   = (uint32_t)(wn * 32 + np * 16 + lnB);
                uint32_t chunk = nb >> 3;
                uint32_t swz = (chunk ^ (krow & 7)) << 4;
                uint32_t bh[4], bl[4];
                ldsm_x4_t(bh, bbase + krow * 256 + swz);
                ldsm_x4_t(bl, bbase + 8192 + krow * 256 + swz);
#pragma unroll
                for (int mi = 0; mi < 4; mi++) {
                    mma_bf16(acc[mi][np*2+0], ah[mi], bh + 0);
                    mma_bf16(acc[mi][np*2+1], ah[mi], bh + 2);
                    mma_bf16(acc[mi][np*2+0], ah[mi], bl + 0);
                    mma_bf16(acc[mi][np*2+1], ah[mi], bl + 2);
                    mma_bf16(acc[mi][np*2+0], al[mi], bh + 0);
                    mma_bf16(acc[mi][np*2+1], al[mi], bh + 2);
                }
            }
        }
        __syncthreads();
    }

    int er = lane >> 2, ec = (lane & 3) * 2;
#pragma unroll
    for (int mi = 0; mi < 4; mi++) {
#pragma unroll
        for (int ni = 0; ni < 4; ni++) {
            int row = co0 + wm * 64 + mi * 16 + er;
            int col = n0 + wn * 32 + ni * 8 + ec;
            size_t g0 = (size_t)(b * CC + row) * HWP + col;
            size_t g1 = g0 + 8 * HWP;
            float2 s0 = *(const float2*)(skip + g0);
            float2 s1 = *(const float2*)(skip + g1);
            float2 o0 = make_float2(acc[mi][ni][0] + s0.x, acc[mi][ni][1] + s0.y);
            float2 o1 = make_float2(acc[mi][ni][2] + s1.x, acc[mi][ni][3] + s1.y);
            *(float2*)(out + g0) = o0;
            *(float2*)(out + g1) = o1;
        }
    }
}

// ===========================================================================
extern "C" void kernel_launch(void* const* d_in, const int* in_sizes, int n_in,
                              void* d_out, int out_size) {
    const float* skip   = (const float*)d_in[0];
    const float* dec    = (const float*)d_in[1];
    const float* w_fea  = (const float*)d_in[2];
    const float* sigma1 = (const float*)d_in[3];
    const float* sigma2 = (const float*)d_in[4];
    const float* mixerw = (const float*)d_in[5];
    float* out = (float*)d_out;

    k_params<<<1, CC>>>(sigma1, sigma2);
    k_wsplit<<<CC*CC/256, 256>>>(mixerw);

    cudaFuncSetAttribute(k_plane, cudaFuncAttributeMaxDynamicSharedMemorySize,
                         PLANE_SMEM);
    k_plane<<<BB*CC, PT, PLANE_SMEM>>>((const float4*)dec, (const float4*)skip,
                                       w_fea);

    cudaFuncSetAttribute(k_gemm_mma, cudaFuncAttributeMaxDynamicSharedMemorySize,
                         GEMM_SMEM);
    dim3 grid(HWP / 128, CC / 128, BB);
    k_gemm_mma<<<grid, 256, GEMM_SMEM>>>(skip, out);
}

// round 11
// speedup vs baseline: 1.2790x; 1.1484x over previous
#include <cuda_runtime.h>
#include <cuda_bf16.h>
#include <math.h>
#include <stdint.h>

// ---- problem constants ----
#define BB 16
#define CC 256
#define HH 96
#define WW 96
#define HWP (HH*WW)                 // 9216
#define NELEM (BB*CC*HWP)           // 37748736
#define S0 24
#define S1 48
#define S2 72

// ---- scratch (device globals: allocation-free rule) ----
__device__ __nv_bfloat16 g_zh[NELEM];
__device__ __nv_bfloat16 g_zl[NELEM];
__device__ __nv_bfloat16 g_wh[CC*CC];
__device__ __nv_bfloat16 g_wl[CC*CC];
__device__ float g_dogk[CC*3];

// ===========================================================================
// PTX helpers
// ===========================================================================
__device__ __forceinline__ uint32_t smem_u32(const void* p) {
    uint32_t a;
    asm("{ .reg .u64 t; cvta.to.shared.u64 t, %1; cvt.u32.u64 %0, t; }"
        : "=r"(a) : "l"(p));
    return a;
}
#define CP16(dst, src) asm volatile( \
    "cp.async.cg.shared.global [%0], [%1], 16;" :: "r"(dst), "l"(src) : "memory")
#define CP_COMMIT() asm volatile("cp.async.commit_group;" ::: "memory")
#define CP_WAIT1() asm volatile("cp.async.wait_group 1;" ::: "memory")
#define CP_WAIT0() asm volatile("cp.async.wait_group 0;" ::: "memory")

__device__ __forceinline__ void ldsm_x4(uint32_t* r, uint32_t addr) {
    asm volatile("ldmatrix.sync.aligned.m8n8.x4.shared.b16 {%0,%1,%2,%3}, [%4];"
                 : "=r"(r[0]), "=r"(r[1]), "=r"(r[2]), "=r"(r[3]) : "r"(addr));
}
__device__ __forceinline__ void ldsm_x4_t(uint32_t* r, uint32_t addr) {
    asm volatile("ldmatrix.sync.aligned.m8n8.x4.trans.shared.b16 {%0,%1,%2,%3}, [%4];"
                 : "=r"(r[0]), "=r"(r[1]), "=r"(r[2]), "=r"(r[3]) : "r"(addr));
}
__device__ __forceinline__ void mma_bf16(float* c, const uint32_t* a, const uint32_t* b) {
    asm volatile(
        "mma.sync.aligned.m16n8k16.row.col.f32.bf16.bf16.f32 "
        "{%0,%1,%2,%3}, {%4,%5,%6,%7}, {%8,%9}, {%0,%1,%2,%3};"
        : "+f"(c[0]), "+f"(c[1]), "+f"(c[2]), "+f"(c[3])
        : "r"(a[0]), "r"(a[1]), "r"(a[2]), "r"(a[3]), "r"(b[0]), "r"(b[1]));
}

// ===========================================================================
// K0: per-channel DoG difference-kernel coefficients
// ===========================================================================
__global__ void k_params(const float* __restrict__ s1r, const float* __restrict__ s2r) {
    int c = threadIdx.x;
    float s1 = 2.f / (1.f + expf(-s1r[c]));
    float s2 = 2.f / (1.f + expf(-s2r[c]));
    float e1 = expf(-1.f / (2.f * s1 * s1)); float q1 = expf(-1.f / (s1 * s1));
    float e2 = expf(-1.f / (2.f * s2 * s2)); float q2 = expf(-1.f / (s2 * s2));
    float n1 = 1.f + 4.f * e1 + 4.f * q1;
    float n2 = 1.f + 4.f * e2 + 4.f * q2;
    g_dogk[c*3+0] = 1.f/n1 - 1.f/n2;
    g_dogk[c*3+1] = e1/n1 - e2/n2;
    g_dogk[c*3+2] = q1/n1 - q2/n2;
}

// K0b: split mixer weight into bf16 hi/lo
__global__ void k_wsplit(const float* __restrict__ w) {
    int i = blockIdx.x * 256 + threadIdx.x;
    float v = w[i];
    __nv_bfloat16 h = __float2bfloat16(v);
    g_wh[i] = h;
    g_wl[i] = __float2bfloat16(v - __bfloat162float(h));
}

// ===========================================================================
// edge_scale: upsample-edge for one scale over a 4-pixel strip (w%4==0).
//   Compile-time xi pattern; taps clamped (exactly reproduces clamped bilinear).
// ===========================================================================
template<int S, int NT, int KSM, int XI0, int XI1, int XI2, int XI3>
__device__ __forceinline__ void edge_scale(
        const float* __restrict__ p, int h, int w, float scl,
        float wx0, float wx1, float wx2, float wx3,
        const float* __restrict__ yc, float* __restrict__ eout) {
    float fy = fmaxf((h + 0.5f) * scl - 0.5f, 0.f);
    int y0 = (int)fy;
    float wy = fy - (float)y0;
    const float* pr0 = p + y0 * S;
    const float* pr1 = p + min(y0 + 1, S - 1) * S;
    int x0 = (w >> 2) * KSM - 1;
    float T0[NT], T1[NT];
#pragma unroll
    for (int q = 0; q < NT; q++) {
        int cq = min(max(x0 + q, 0), S - 1);
        T0[q] = pr0[cq];
        T1[q] = pr1[cq];
    }
    const int xiv[4] = { XI0, XI1, XI2, XI3 };
    const float wxv[4] = { wx0, wx1, wx2, wx3 };
#pragma unroll
    for (int px = 0; px < 4; px++) {
        const int xi = xiv[px];
        float wx = wxv[px];
        float top = T0[xi] + (T0[xi+1] - T0[xi]) * wx;
        float bot = T1[xi] + (T1[xi+1] - T1[xi]) * wx;
        float up = top + (bot - top) * wy;
        eout[px] = fabsf(yc[px] - up);
    }
}

// ===========================================================================
// K1: fused per-plane elementwise chain. One CTA / (b,c) plane, 512 threads.
//   Phase 3: 4-pixel strips, compile-time x-geometry (no tables, no selects).
// ===========================================================================
#define SMF_Y  0
#define SMF_D0 9216
#define SMF_D1 (9216+576)
#define SMF_D2 (9216+2880)
#define PLANE_SMEM ((9216+8064)*4)   // 69120 B dynamic
#define PT 512

__global__ void __launch_bounds__(PT) k_plane(const float4* __restrict__ dec,
                                              const float4* __restrict__ skip,
                                              const float* __restrict__ wfea) {
    extern __shared__ float sm[];
    __shared__ int   s_di[144];
    __shared__ float s_dw[144];

    int bc = blockIdx.x;
    int c  = bc % CC;
    int t  = threadIdx.x;

    // 0) downsample coordinate tables (used by phase 2 only)
    if (t < 144) {
        int u = t;
        int s = (u < 24) ? 0 : (u < 72) ? 1 : 2;
        int o = (s == 0) ? u : (s == 1) ? u - 24 : u - 72;
        float sf = (s == 0) ? (96.f/S0) : (s == 1) ? (96.f/S1) : (96.f/S2);
        float f = fmaxf((o + 0.5f) * sf - 0.5f, 0.f);
        int i0 = (int)f;
        s_di[u] = i0;
        s_dw[u] = f - (float)i0;
    }

    // 1) y = dec + skip into smem
    const float4* dp = dec  + (size_t)bc * (HWP/4);
    const float4* sp = skip + (size_t)bc * (HWP/4);
    float4* y4 = (float4*)(sm + SMF_Y);
#pragma unroll
    for (int k = 0; k < 5; k++) {
        int i = k * PT + t;
        if (i < HWP/4) {
            float4 a = dp[i], b = sp[i];
            y4[i] = make_float4(a.x + b.x, a.y + b.y, a.z + b.z, a.w + b.w);
        }
    }
    __syncthreads();

    const float* sy = sm + SMF_Y;

    // 2) three bilinear downsamples into smem (8064 outputs) via tables
#pragma unroll
    for (int k = 0; k < 16; k++) {
        int i = k * PT + t;
        if (i >= 8064) break;
        int S, off, o, tb;
        if (i < 576)       { S = S0; off = SMF_D0; o = i;        tb = 0;  }
        else if (i < 2880) { S = S1; off = SMF_D1; o = i - 576;  tb = 24; }
        else               { S = S2; off = SMF_D2; o = i - 2880; tb = 72; }
        int oy = o / S, ox = o % S;
        int y0 = s_di[tb + oy];  float wy = s_dw[tb + oy];
        int x0 = s_di[tb + ox];  float wx = s_dw[tb + ox];
        int r0 = y0 * WW, r1 = min(y0 + 1, HH - 1) * WW;
        int x1 = min(x0 + 1, WW - 1);
        float v00 = sy[r0 + x0], v01 = sy[r0 + x1];
        float v10 = sy[r1 + x0], v11 = sy[r1 + x1];
        sm[off + o] = (v00*(1.f-wx) + v01*wx)*(1.f-wy) + (v10*(1.f-wx) + v11*wx)*wy;
    }
    __syncthreads();

    // 3) fused edges + DoG + combine -> zh/zl: 4-pixel strips
    float dC = g_dogk[c*3+0], dE = g_dogk[c*3+1], dX = g_dogk[c*3+2];
    float wf = wfea[c];
    const float* p0 = sm + SMF_D0;
    const float* p1 = sm + SMF_D1;
    const float* p2 = sm + SMF_D2;
    size_t gbase = (size_t)bc * HWP;
    uint2* zh4 = (uint2*)(g_zh + gbase);
    uint2* zl4 = (uint2*)(g_zl + gbase);

#pragma unroll
    for (int k = 0; k < 5; k++) {
        int j = k * PT + t;                 // strip index 0..2303 (24 per row)
        if (j < 2304) {
            int h = j / 24, w = 4 * (j % 24);

            // ---- DoG window: 3 rows x 6 cols (float4 middle + 2 edge taps) ----
            float R[3][6];
            bool wl = w > 0, wr = w < WW - 4;
#pragma unroll
            for (int r = 0; r < 3; r++) {
                int hr = h - 1 + r;
                if (hr >= 0 && hr < HH) {
                    const float* rowp = sy + hr * WW;
                    float4 m = *(const float4*)(rowp + w);   // w%4==0: aligned
                    R[r][1] = m.x; R[r][2] = m.y; R[r][3] = m.z; R[r][4] = m.w;
                    R[r][0] = wl ? rowp[w - 1] : 0.f;
                    R[r][5] = wr ? rowp[w + 4] : 0.f;
                } else {
#pragma unroll
                    for (int q = 0; q < 6; q++) R[r][q] = 0.f;
                }
            }
            float yc[4], dog[4];
#pragma unroll
            for (int px = 0; px < 4; px++) {
                yc[px] = R[1][px + 1];
                dog[px] = dC * R[1][px+1]
                        + dE * (R[0][px+1] + R[2][px+1] + R[1][px] + R[1][px+2])
                        + dX * (R[0][px] + R[0][px+2] + R[2][px] + R[2][px+2]);
            }

            // ---- multi-scale edges: compile-time x-geometry ----
            float e0[4], e1[4], e2[4];
            edge_scale<S0, 3, 1, 0,0,1,1>(p0, h, w, 0.25f,
                0.625f, 0.875f, 0.125f, 0.375f, yc, e0);
            edge_scale<S1, 4, 2, 0,1,1,2>(p1, h, w, 0.5f,
                0.75f, 0.25f, 0.75f, 0.25f, yc, e1);
            edge_scale<S2, 5, 3, 0,1,2,3>(p2, h, w, 0.75f,
                0.875f, 0.625f, 0.375f, 0.125f, yc, e2);

            // ---- combine + bf16 split, 8B stores ----
            uint32_t hp[2], lp[2];
#pragma unroll
            for (int half = 0; half < 2; half++) {
                float v[2];
#pragma unroll
                for (int q = 0; q < 2; q++) {
                    int px = half * 2 + q;
                    float a01 = fabsf(e0[px] - e1[px]);
                    float a02 = fabsf(e0[px] - e2[px]);
                    float a12 = fabsf(e1[px] - e2[px]);
                    float we = (a01 + a02 + a12) * (1.f/3.f);
                    v[q] = 3.f*yc[px] + wf*we + dog[px];
                }
                __nv_bfloat16 h0 = __float2bfloat16(v[0]);
                __nv_bfloat16 h1 = __float2bfloat16(v[1]);
                __nv_bfloat16 l0 = __float2bfloat16(v[0] - __bfloat162float(h0));
                __nv_bfloat16 l1 = __float2bfloat16(v[1] - __bfloat162float(h1));
                hp[half] = ((uint32_t)__bfloat16_as_ushort(h1) << 16)
                         |  (uint32_t)__bfloat16_as_ushort(h0);
                lp[half] = ((uint32_t)__bfloat16_as_ushort(l1) << 16)
                         |  (uint32_t)__bfloat16_as_ushort(l0);
            }
            zh4[j] = make_uint2(hp[0], hp[1]);
            zl4[j] = make_uint2(lp[0], lp[1]);
        }
    }
}

// ===========================================================================
// K4: HMMA split-bf16 GEMM (exact R4/R6 config, measured ~174-176us)
// ===========================================================================
#define ABUF_SZ 10240
#define BUF_STRIDE 36864            // 2*10240 + 2*8192
#define GEMM_SMEM (2*BUF_STRIDE)    // 73728

__global__ void __launch_bounds__(256, 2) k_gemm_mma(
        const float* __restrict__ skip, float* __restrict__ out) {
    extern __shared__ char smem_raw[];
    uint32_t sb = smem_u32(smem_raw);

    int t = threadIdx.x, wid = t >> 5, lane = t & 31;
    int wm = wid & 1, wn = wid >> 1;
    int b = blockIdx.z, co0 = blockIdx.y * 128, n0 = blockIdx.x * 128;

    const __nv_bfloat16* whlo[2] = { g_wh, g_wl };
    const __nv_bfloat16* zhlo[2] = { g_zh, g_zl };

    auto load_chunk = [&](int kc, int d) {
        uint32_t base = sb + d * BUF_STRIDE;
#pragma unroll
        for (int j = 0; j < 4; j++) {            // A
            int idx = j * 256 + t;
            int hl = idx >> 9, rem = idx & 511;
            int row = rem >> 2, c = rem & 3;
            const __nv_bfloat16* src = whlo[hl] + (co0 + row) * CC + kc * 32 + c * 8;
            CP16(base + hl * ABUF_SZ + row * 80 + c * 16, src);
        }
#pragma unroll
        for (int j = 0; j < 4; j++) {            // B
            int idx = j * 256 + t;
            int hl = idx >> 9, rem = idx & 511;
            int row = rem >> 4, c = rem & 15;
            const __nv_bfloat16* src = zhlo[hl]
                + (size_t)(b * CC + kc * 32 + row) * HWP + n0 + c * 8;
            CP16(base + 2 * ABUF_SZ + hl * 8192 + row * 256
                 + (uint32_t)((c ^ (row & 7)) << 4), src);
        }
    };

    float acc[4][4][4];
#pragma unroll
    for (int i = 0; i < 4; i++)
#pragma unroll
        for (int j = 0; j < 4; j++)
#pragma unroll
            for (int k = 0; k < 4; k++) acc[i][j][k] = 0.f;

    int lt = lane >> 3;
    int lrA = (lane & 7) + ((lt & 1) << 3);
    int lcA = (lt >> 1) << 4;
    int lkB = (lane & 7) + ((lt & 1) << 3);
    int lnB = (lt >> 1) << 3;

    load_chunk(0, 0);
    CP_COMMIT();

    for (int kc = 0; kc < 8; kc++) {
        int d = kc & 1;
        if (kc + 1 < 8) { load_chunk(kc + 1, d ^ 1); CP_COMMIT(); CP_WAIT1(); }
        else           { CP_WAIT0(); }
        __syncthreads();

        uint32_t abase = sb + d * BUF_STRIDE;
        uint32_t bbase = abase + 2 * ABUF_SZ;

#pragma unroll
        for (int ks = 0; ks < 2; ks++) {
            uint32_t ah[4][4], al[4][4];
#pragma unroll
            for (int mi = 0; mi < 4; mi++) {
                uint32_t arow = (uint32_t)(wm * 64 + mi * 16 + lrA);
                ldsm_x4(ah[mi], abase + arow * 80 + ks * 32 + lcA);
                ldsm_x4(al[mi], abase + ABUF_SZ + arow * 80 + ks * 32 + lcA);
            }
#pragma unroll
            for (int np = 0; np < 2; np++) {
                uint32_t krow = (uint32_t)(ks * 16 + lkB);
                uint32_t nb   = (uint32_t)(wn * 32 + np * 16 + lnB);
                uint32_t chunk = nb >> 3;
                uint32_t swz = (chunk ^ (krow & 7)) << 4;
                uint32_t bh[4], bl[4];
                ldsm_x4_t(bh, bbase + krow * 256 + swz);
                ldsm_x4_t(bl, bbase + 8192 + krow * 256 + swz);
#pragma unroll
                for (int mi = 0; mi < 4; mi++) {
                    mma_bf16(acc[mi][np*2+0], ah[mi], bh + 0);
                    mma_bf16(acc[mi][np*2+1], ah[mi], bh + 2);
                    mma_bf16(acc[mi][np*2+0], ah[mi], bl + 0);
                    mma_bf16(acc[mi][np*2+1], ah[mi], bl + 2);
                    mma_bf16(acc[mi][np*2+0], al[mi], bh + 0);
                    mma_bf16(acc[mi][np*2+1], al[mi], bh + 2);
                }
            }
        }
        __syncthreads();
    }

    int er = lane >> 2, ec = (lane & 3) * 2;
#pragma unroll
    for (int mi = 0; mi < 4; mi++) {
#pragma unroll
        for (int ni = 0; ni < 4; ni++) {
            int row = co0 + wm * 64 + mi * 16 + er;
            int col = n0 + wn * 32 + ni * 8 + ec;
            size_t g0 = (size_t)(b * CC + row) * HWP + col;
            size_t g1 = g0 + 8 * HWP;
            float2 s0 = *(const float2*)(skip + g0);
            float2 s1 = *(const float2*)(skip + g1);
            float2 o0 = make_float2(acc[mi][ni][0] + s0.x, acc[mi][ni][1] + s0.y);
            float2 o1 = make_float2(acc[mi][ni][2] + s1.x, acc[mi][ni][3] + s1.y);
            *(float2*)(out + g0) = o0;
            *(float2*)(out + g1) = o1;
        }
    }
}

// ===========================================================================
extern "C" void kernel_launch(void* const* d_in, const int* in_sizes, int n_in,
                              void* d_out, int out_size) {
    const float* skip   = (const float*)d_in[0];
    const float* dec    = (const float*)d_in[1];
    const float* w_fea  = (const float*)d_in[2];
    const float* sigma1 = (const float*)d_in[3];
    const float* sigma2 = (const float*)d_in[4];
    const float* mixerw = (const float*)d_in[5];
    float* out = (float*)d_out;

    k_params<<<1, CC>>>(sigma1, sigma2);
    k_wsplit<<<CC*CC/256, 256>>>(mixerw);

    cudaFuncSetAttribute(k_plane, cudaFuncAttributeMaxDynamicSharedMemorySize,
                         PLANE_SMEM);
    k_plane<<<BB*CC, PT, PLANE_SMEM>>>((const float4*)dec, (const float4*)skip,
                                       w_fea);

    cudaFuncSetAttribute(k_gemm_mma, cudaFuncAttributeMaxDynamicSharedMemorySize,
                         GEMM_SMEM);
    dim3 grid(HWP / 128, CC / 128, BB);
    k_gemm_mma<<<grid, 256, GEMM_SMEM>>>(skip, out);
}